// round 6
// baseline (speedup 1.0000x reference)
#include <cuda_runtime.h>
#include <cuda_bf16.h>
#include <math.h>
#include <stdint.h>

// loss = mean_i ||v0_i - v1_i|| + 0.5 * sum_views mean_i [ log(sum_{j!=i} exp(-d_ij)) - log(N-1) ]
// d_ij = max(sqrt(max(|zi|^2+|zj|^2-2 zi.zj, 0)), 1e-12)
//
// Gram via mma.sync pure bf16 (verified rel_err ~1.3e-5). Symmetric upper-tri
// 128x128 tiles; each tile feeds row AND col sums. PERSISTENT CTAs (2/SM) with
// a flattened (tile, chunk) cp.async pipeline: the next tile's first chunk is
// prefetched during the current tile's last compute + epilogue, eliminating the
// per-tile cold-start bubble and overlapping the epilogue with loads.

namespace {
constexpr int N  = 8192;
constexpr int D  = 256;
constexpr int BM = 128;
constexpr int NT = N / BM;               // 64
constexpr int NTRI = NT * (NT + 1) / 2;  // 2080
constexpr int NTILES = 2 * NTRI;         // both views
constexpr int PCTAS = 296;               // 2 CTAs x 148 SMs, persistent

constexpr int KCHUNK  = 64;              // bf16 k per chunk
constexpr int NCHUNK  = D / KCHUNK;      // 4
constexpr int PITCHB  = 144;             // smem row pitch (128 payload + 16 pad)
constexpr int TILEB   = BM * PITCHB;     // 18432 per operand tile
constexpr int BUFB    = 2 * TILEB;       // A + B per stage
constexpr int SM_SQI  = 2 * BUFB;        // 73728
constexpr int SM_SQJ  = SM_SQI + 512;
constexpr int SM_ROW  = SM_SQJ + 512;    // 4 x 128 f32
constexpr int SM_COL  = SM_ROW + 2048;   // 2 x 128 f32
constexpr int SMEM_TOTAL = SM_COL + 1024;  // 77824 -> 2 CTAs/SM
}

__device__ __align__(16) __nv_bfloat16 g_bf[2][N][D];
__device__ __align__(16) float g_sq[2][N];
__device__ __align__(16) float g_alignRow[N];
__device__ __align__(16) float g_part[2][NT][N];

// ---------------- PTX helpers (stable ISA only) -----------------------------
__device__ __forceinline__ uint32_t smem_u32(const void* p) {
    uint32_t a;
    asm("{ .reg .u64 t; cvta.to.shared.u64 t, %1; cvt.u32.u64 %0, t; }" : "=r"(a) : "l"(p));
    return a;
}
__device__ __forceinline__ void cpasync16(uint32_t dst, const void* src) {
    asm volatile("cp.async.cg.shared.global [%0], [%1], 16;" :: "r"(dst), "l"(src) : "memory");
}
#define CP_COMMIT()  asm volatile("cp.async.commit_group;" ::: "memory")
#define CP_WAIT(n)   asm volatile("cp.async.wait_group %0;" :: "n"(n) : "memory")

__device__ __forceinline__ void ldsm4(uint32_t* r, uint32_t addr) {
    asm volatile("ldmatrix.sync.aligned.m8n8.x4.shared.b16 {%0,%1,%2,%3}, [%4];"
                 : "=r"(r[0]), "=r"(r[1]), "=r"(r[2]), "=r"(r[3]) : "r"(addr));
}
__device__ __forceinline__ void mma16816(float* c, const uint32_t* a, uint32_t b0, uint32_t b1) {
    asm volatile(
        "mma.sync.aligned.m16n8k16.row.col.f32.bf16.bf16.f32 "
        "{%0,%1,%2,%3}, {%4,%5,%6,%7}, {%8,%9}, {%0,%1,%2,%3};"
        : "+f"(c[0]), "+f"(c[1]), "+f"(c[2]), "+f"(c[3])
        : "r"(a[0]), "r"(a[1]), "r"(a[2]), "r"(a[3]), "r"(b0), "r"(b1));
}
__device__ __forceinline__ float fsqrt_approx(float x) {
    float r; asm("sqrt.approx.f32 %0, %1;" : "=f"(r) : "f"(x)); return r;
}

__device__ __forceinline__ void decode_tile(int l, int& view, int& ti, int& tj) {
    view = (l >= NTRI) ? 1 : 0;
    int u = l - view * NTRI;
    int t = (int)((sqrtf(8.f * (float)u + 1.f) - 1.f) * 0.5f);
    while ((t + 1) * (t + 2) / 2 <= u) ++t;
    while (t * (t + 1) / 2 > u) --t;
    tj = t;
    ti = u - t * (t + 1) / 2;
}

// ---------------------------------------------------------------------------
// Kernel 1: fp32 -> bf16; squared norms (fp32); align row norms.
// ---------------------------------------------------------------------------
__global__ void convert_kernel(const float* __restrict__ v0, const float* __restrict__ v1) {
    int row  = blockIdx.x * blockDim.y + threadIdx.y;
    int lane = threadIdx.x;
    const float4* r0 = reinterpret_cast<const float4*>(v0 + (size_t)row * D);
    const float4* r1 = reinterpret_cast<const float4*>(v1 + (size_t)row * D);
    __nv_bfloat162* h0 = reinterpret_cast<__nv_bfloat162*>(&g_bf[0][row][0]);
    __nv_bfloat162* h1 = reinterpret_cast<__nv_bfloat162*>(&g_bf[1][row][0]);

    float s0 = 0.f, s1 = 0.f, sd = 0.f;
#pragma unroll
    for (int c = lane; c < D / 4; c += 32) {
        float4 a = r0[c], b = r1[c];
        s0 += a.x*a.x + a.y*a.y + a.z*a.z + a.w*a.w;
        s1 += b.x*b.x + b.y*b.y + b.z*b.z + b.w*b.w;
        float dx=a.x-b.x, dy=a.y-b.y, dz=a.z-b.z, dw=a.w-b.w;
        sd += dx*dx + dy*dy + dz*dz + dw*dw;
        h0[2*c]   = __halves2bfloat162(__float2bfloat16(a.x), __float2bfloat16(a.y));
        h0[2*c+1] = __halves2bfloat162(__float2bfloat16(a.z), __float2bfloat16(a.w));
        h1[2*c]   = __halves2bfloat162(__float2bfloat16(b.x), __float2bfloat16(b.y));
        h1[2*c+1] = __halves2bfloat162(__float2bfloat16(b.z), __float2bfloat16(b.w));
    }
#pragma unroll
    for (int off = 16; off > 0; off >>= 1) {
        s0 += __shfl_down_sync(0xffffffffu, s0, off);
        s1 += __shfl_down_sync(0xffffffffu, s1, off);
        sd += __shfl_down_sync(0xffffffffu, sd, off);
    }
    if (lane == 0) {
        g_sq[0][row] = s0;
        g_sq[1][row] = s1;
        g_alignRow[row] = sqrtf(sd);
    }
}

// ---------------------------------------------------------------------------
// Kernel 2: persistent symmetric Gram + exp(-d) row/col sums via mma.sync bf16.
// 296 CTAs x 256 threads; each CTA walks tiles l = bid + k*296.
// ---------------------------------------------------------------------------
__global__ __launch_bounds__(256, 2)
void gram_mma_kernel() {
    extern __shared__ char smem[];
    const uint32_t sb = smem_u32(smem);
    const int tid = threadIdx.x;
    const int lid = tid & 31;
    const int wid = tid >> 5;
    const int wm = wid >> 2;          // 0..1
    const int wn = wid & 3;           // 0..3

    float* sqi_s = reinterpret_cast<float*>(smem + SM_SQI);
    float* sqj_s = reinterpret_cast<float*>(smem + SM_SQJ);
    float* s_row = reinterpret_cast<float*>(smem + SM_ROW);   // [4][128]
    float* s_col = reinterpret_cast<float*>(smem + SM_COL);   // [2][128]

    // ldmatrix lane-invariant offsets
    const int rA = (lid & 7) | (((lid >> 3) & 1) << 3);
    const int cB = (lid >> 4) * 8;
    uint32_t aoff[4], boff[2];
#pragma unroll
    for (int mt = 0; mt < 4; mt++) aoff[mt] = (uint32_t)((wm*64 + mt*16 + rA) * PITCHB + cB*2);
#pragma unroll
    for (int np = 0; np < 2; np++) boff[np] = (uint32_t)((wn*32 + np*16 + rA) * PITCHB + cB*2);

    // ---- loader: one K-chunk of tile (i0,j0,view) into buffer b ----
    auto load_chunk = [&](int view, int i0, int j0, int c, int b) {
        const int kt = c * KCHUNK;
        const uint32_t base = sb + b * BUFB;
        const __nv_bfloat16* A = &g_bf[view][i0][0];
        const __nv_bfloat16* B = &g_bf[view][j0][0];
#pragma unroll
        for (int it = 0; it < 8; it++) {
            const int t   = it >> 2;
            const int rem = (it & 3) * 256 + tid;
            const int row = rem >> 3;
            const int u   = rem & 7;
            const __nv_bfloat16* src = (t == 0 ? A : B) + (size_t)row * D + kt + u * 8;
            cpasync16(base + t * TILEB + row * PITCHB + u * 16, src);
        }
        CP_COMMIT();
    };

    // current tile state
    int l = blockIdx.x;
    if (l >= NTILES) return;
    int view, ti, tj;
    decode_tile(l, view, ti, tj);
    int i0 = ti * BM, j0 = tj * BM;

    // prime the pipeline: chunk 0 of the first tile
    load_chunk(view, i0, j0, 0, 0);

    while (true) {
        // next tile (for cross-tile prefetch)
        const int ln = l + PCTAS;
        int viewn = 0, tin = 0, tjn = 0, i0n = 0, j0n = 0;
        const bool has_next = (ln < NTILES);
        if (has_next) { decode_tile(ln, viewn, tin, tjn); i0n = tin * BM; j0n = tjn * BM; }

        if (tid < 128) {
            sqi_s[tid] = g_sq[view][i0 + tid];
            sqj_s[tid] = g_sq[view][j0 + tid];
        }

        float acc[4][4][4];
#pragma unroll
        for (int a = 0; a < 4; a++)
#pragma unroll
            for (int b = 0; b < 4; b++)
#pragma unroll
                for (int q = 0; q < 4; q++) acc[a][b][q] = 0.f;

        for (int c = 0; c < NCHUNK; c++) {
            const int b = c & 1;
            // prefetch next step in the flattened (tile, chunk) sequence
            bool prefetched = true;
            if (c + 1 < NCHUNK)      load_chunk(view, i0, j0, c + 1, b ^ 1);
            else if (has_next)       load_chunk(viewn, i0n, j0n, 0, b ^ 1);
            else                     prefetched = false;
            if (prefetched) { CP_WAIT(1); } else { CP_WAIT(0); }
            __syncthreads();

            const uint32_t bA = sb + b * BUFB + 0 * TILEB;
            const uint32_t bB = sb + b * BUFB + 1 * TILEB;
#pragma unroll
            for (int ks = 0; ks < KCHUNK / 16; ks++) {
                const uint32_t ko = ks * 32;
                uint32_t A[4][4], B[2][4];
#pragma unroll
                for (int mt = 0; mt < 4; mt++) ldsm4(A[mt], bA + aoff[mt] + ko);
#pragma unroll
                for (int np = 0; np < 2; np++) ldsm4(B[np], bB + boff[np] + ko);
#pragma unroll
                for (int mt = 0; mt < 4; mt++) {
#pragma unroll
                    for (int nt = 0; nt < 4; nt++) {
                        const int np = nt >> 1, sel = nt & 1;
                        mma16816(acc[mt][nt], A[mt], B[np][sel], B[np][2 + sel]);
                    }
                }
            }
            __syncthreads();
        }

        // ---- Epilogue (overlaps next tile's chunk-0 load) ----
        const bool diag = (ti == tj);
        float rsum[4][2], csum[4][2];
#pragma unroll
        for (int q = 0; q < 4; q++) { rsum[q][0]=rsum[q][1]=0.f; csum[q][0]=csum[q][1]=0.f; }

#pragma unroll
        for (int mt = 0; mt < 4; mt++) {
            const int r0 = wm*64 + mt*16 + (lid >> 2);
            const float sqr0 = sqi_s[r0], sqr1 = sqi_s[r0 + 8];
#pragma unroll
            for (int nt = 0; nt < 4; nt++) {
                const int c0 = wn*32 + nt*8 + 2*(lid & 3);
                const float sqc0 = sqj_s[c0], sqc1 = sqj_s[c0 + 1];
                const float* a = acc[mt][nt];
                float d2, d, e00, e01, e10, e11;
                d2 = fmaxf(sqr0 + sqc0 - 2.f*a[0], 0.f); d = fmaxf(fsqrt_approx(d2), 1e-12f);
                e00 = (diag && r0 == c0) ? 0.f : __expf(-d);
                d2 = fmaxf(sqr0 + sqc1 - 2.f*a[1], 0.f); d = fmaxf(fsqrt_approx(d2), 1e-12f);
                e01 = (diag && r0 == c0 + 1) ? 0.f : __expf(-d);
                d2 = fmaxf(sqr1 + sqc0 - 2.f*a[2], 0.f); d = fmaxf(fsqrt_approx(d2), 1e-12f);
                e10 = (diag && r0 + 8 == c0) ? 0.f : __expf(-d);
                d2 = fmaxf(sqr1 + sqc1 - 2.f*a[3], 0.f); d = fmaxf(fsqrt_approx(d2), 1e-12f);
                e11 = (diag && r0 + 8 == c0 + 1) ? 0.f : __expf(-d);
                rsum[mt][0] += e00 + e01;
                rsum[mt][1] += e10 + e11;
                csum[nt][0] += e00 + e10;
                csum[nt][1] += e01 + e11;
            }
        }

#pragma unroll
        for (int mt = 0; mt < 4; mt++) {
            float v0 = rsum[mt][0], v1 = rsum[mt][1];
            v0 += __shfl_xor_sync(0xffffffffu, v0, 1); v0 += __shfl_xor_sync(0xffffffffu, v0, 2);
            v1 += __shfl_xor_sync(0xffffffffu, v1, 1); v1 += __shfl_xor_sync(0xffffffffu, v1, 2);
            if ((lid & 3) == 0) {
                const int r = wm*64 + mt*16 + (lid >> 2);
                s_row[wn*128 + r]     = v0;
                s_row[wn*128 + r + 8] = v1;
            }
        }
#pragma unroll
        for (int nt = 0; nt < 4; nt++) {
            float u0 = csum[nt][0], u1 = csum[nt][1];
#pragma unroll
            for (int off = 4; off < 32; off <<= 1) {
                u0 += __shfl_xor_sync(0xffffffffu, u0, off);
                u1 += __shfl_xor_sync(0xffffffffu, u1, off);
            }
            if (lid < 4) {
                const int cc = wn*32 + nt*8 + 2*lid;
                s_col[wm*128 + cc]     = u0;
                s_col[wm*128 + cc + 1] = u1;
            }
        }
        __syncthreads();

        if (tid < 128) {
            float rv = s_row[tid] + s_row[128 + tid] + s_row[256 + tid] + s_row[384 + tid];
            g_part[view][tj][i0 + tid] = rv;
            if (ti != tj) {
                float cv = s_col[tid] + s_col[128 + tid];
                g_part[view][ti][j0 + tid] = cv;
            }
        }
        __syncthreads();   // protect sqi_s/sqj_s rewrite on next iteration

        if (!has_next) break;
        l = ln; view = viewn; ti = tin; tj = tjn; i0 = i0n; j0 = j0n;
    }
}

// ---------------------------------------------------------------------------
// Kernel 3: finalize with fp64 accumulation.
// ---------------------------------------------------------------------------
__global__ void finalize_kernel(float* __restrict__ out) {
    __shared__ double sh0[256], sh1[256], sh2[256];
    const int tid = threadIdx.x;
    double a = 0.0, e0 = 0.0, e1 = 0.0;
    for (int i = tid; i < N; i += 256) {
        a += (double)g_alignRow[i];
        float s0 = 0.f, s1 = 0.f;
#pragma unroll
        for (int c = 0; c < NT; c++) {
            s0 += g_part[0][c][i];
            s1 += g_part[1][c][i];
        }
        e0 += log((double)s0);
        e1 += log((double)s1);
    }
    sh0[tid] = a; sh1[tid] = e0; sh2[tid] = e1;
    __syncthreads();
    for (int off = 128; off > 0; off >>= 1) {
        if (tid < off) {
            sh0[tid] += sh0[tid + off];
            sh1[tid] += sh1[tid + off];
            sh2[tid] += sh2[tid + off];
        }
        __syncthreads();
    }
    if (tid == 0) {
        const double inv_n = 1.0 / (double)N;
        const double logm  = log((double)(N - 1));
        double align   = sh0[0] * inv_n;
        double entropy = 0.5 * ((sh1[0] * inv_n - logm) + (sh2[0] * inv_n - logm));
        out[0] = (float)(align + entropy);
    }
}

// ---------------------------------------------------------------------------
extern "C" void kernel_launch(void* const* d_in, const int* in_sizes, int n_in,
                              void* d_out, int out_size) {
    const float* v0 = (const float*)d_in[0];
    const float* v1 = (const float*)d_in[1];
    float* out = (float*)d_out;

    cudaFuncSetAttribute(gram_mma_kernel, cudaFuncAttributeMaxDynamicSharedMemorySize, SMEM_TOTAL);

    convert_kernel<<<N / 8, dim3(32, 8)>>>(v0, v1);
    gram_mma_kernel<<<PCTAS, 256, SMEM_TOTAL>>>();
    finalize_kernel<<<1, 256>>>(out);
}